// round 3
// baseline (speedup 1.0000x reference)
#include <cuda_runtime.h>
#include <math.h>

// Problem dims (fixed)
#define Bsz  4
#define Lseq 2048
#define Dm   1024
#define Hn   16
#define DKh  64
#define DFFn 4096
#define NTOK (Bsz * Lseq)   // 8192

// ---------------- scratch (no cudaMalloc allowed) ----------------
__device__ float g_x[(size_t)NTOK * Dm];
__device__ float g_q[(size_t)NTOK * Dm];
__device__ float g_k[(size_t)NTOK * Dm];
__device__ float g_v[(size_t)NTOK * Dm];
__device__ float g_o[(size_t)NTOK * Dm];
__device__ float g_y[(size_t)NTOK * Dm];
__device__ float g_z[(size_t)NTOK * Dm];
__device__ float g_h[(size_t)NTOK * DFFn];

// ---------------- LayerNorm: one block (256 thr) per row of 1024 ----------------
__global__ __launch_bounds__(256) void ln_kernel(const float* __restrict__ x,
                                                 const float* __restrict__ g,
                                                 const float* __restrict__ b,
                                                 float* __restrict__ out)
{
    __shared__ float red[256];
    const size_t row = blockIdx.x;
    const int tid = threadIdx.x;
    float4 v = ((const float4*)(x + row * Dm))[tid];

    red[tid] = v.x + v.y + v.z + v.w;
    __syncthreads();
    for (int o = 128; o > 0; o >>= 1) {
        if (tid < o) red[tid] += red[tid + o];
        __syncthreads();
    }
    const float mu = red[0] * (1.0f / Dm);
    __syncthreads();

    const float dx = v.x - mu, dy = v.y - mu, dz = v.z - mu, dw = v.w - mu;
    red[tid] = dx * dx + dy * dy + dz * dz + dw * dw;
    __syncthreads();
    for (int o = 128; o > 0; o >>= 1) {
        if (tid < o) red[tid] += red[tid + o];
        __syncthreads();
    }
    const float inv = rsqrtf(red[0] * (1.0f / Dm) + 1e-6f);

    const float4 gg = ((const float4*)g)[tid];
    const float4 bb = ((const float4*)b)[tid];
    float4 o4;
    o4.x = dx * inv * gg.x + bb.x;
    o4.y = dy * inv * gg.y + bb.y;
    o4.z = dz * inv * gg.z + bb.z;
    o4.w = dw * inv * gg.w + bb.w;
    ((float4*)(out + row * Dm))[tid] = o4;
}

// ---------------- Generic NT GEMM: C[M,N] = A[M,K] @ W[N,K]^T (+ epilogue) ----------------
// 128x128 tile, BK=8, 256 threads, 8x8 per thread.
// EPI: 0 = alpha*acc ; 1 = acc + resid ; 2 = relu(acc + bias[n]) ; 3 = acc + bias[n] + resid
template <int EPI>
__global__ __launch_bounds__(256) void gemm_nt(const float* __restrict__ A,
                                               const float* __restrict__ W,
                                               float* __restrict__ C,
                                               int M, int N, int K,
                                               const float* __restrict__ bias,
                                               const float* __restrict__ resid,
                                               float alpha)
{
    __shared__ float As[8][128];
    __shared__ float Ws[8][128];
    const int tid = threadIdx.x;
    const int m0 = blockIdx.y * 128;
    const int n0 = blockIdx.x * 128;
    const int lrow = tid >> 1;          // 0..127
    const int lcol = (tid & 1) * 4;     // 0 or 4
    const int tx = tid & 15, ty = tid >> 4;

    const float* Ap = A + (size_t)(m0 + lrow) * K + lcol;
    const float* Wp = W + (size_t)(n0 + lrow) * K + lcol;

    float acc[8][8];
#pragma unroll
    for (int i = 0; i < 8; i++)
#pragma unroll
        for (int j = 0; j < 8; j++) acc[i][j] = 0.f;

    for (int k0 = 0; k0 < K; k0 += 8) {
        float4 av = *(const float4*)(Ap + k0);
        float4 wv = *(const float4*)(Wp + k0);
        As[lcol + 0][lrow] = av.x; As[lcol + 1][lrow] = av.y;
        As[lcol + 2][lrow] = av.z; As[lcol + 3][lrow] = av.w;
        Ws[lcol + 0][lrow] = wv.x; Ws[lcol + 1][lrow] = wv.y;
        Ws[lcol + 2][lrow] = wv.z; Ws[lcol + 3][lrow] = wv.w;
        __syncthreads();
#pragma unroll
        for (int kk = 0; kk < 8; kk++) {
            float a[8], w[8];
#pragma unroll
            for (int i = 0; i < 8; i++) a[i] = As[kk][ty * 8 + i];
#pragma unroll
            for (int j = 0; j < 8; j++) w[j] = Ws[kk][tx * 8 + j];
#pragma unroll
            for (int i = 0; i < 8; i++)
#pragma unroll
                for (int j = 0; j < 8; j++)
                    acc[i][j] = fmaf(a[i], w[j], acc[i][j]);
        }
        __syncthreads();
    }

#pragma unroll
    for (int i = 0; i < 8; i++) {
        const int m = m0 + ty * 8 + i;
#pragma unroll
        for (int j = 0; j < 8; j++) {
            const int n = n0 + tx * 8 + j;
            float v = acc[i][j];
            if (EPI == 0)      v *= alpha;
            else if (EPI == 1) v += resid[(size_t)m * N + n];
            else if (EPI == 2) v = fmaxf(v + bias[n], 0.f);
            else if (EPI == 3) v += bias[n] + resid[(size_t)m * N + n];
            C[(size_t)m * N + n] = v;
        }
    }
}

// ---------------- Scores: S[b,h,q,k] = (Q/8 . K) * prior[b,q,k] ; masked -> -1e9 ----------------
// Q is pre-scaled by 1/8 in its projection epilogue.
__global__ __launch_bounds__(256) void scores_kernel(const float* __restrict__ Q,
                                                     const float* __restrict__ Km,
                                                     const float* __restrict__ prior,
                                                     const int* __restrict__ mask,
                                                     float* __restrict__ attn)
{
    __shared__ float Qs[8][128];
    __shared__ float Ks[8][128];
    const int bh = blockIdx.z, b = bh >> 4, h = bh & 15;
    const int m0 = blockIdx.y * 128, n0 = blockIdx.x * 128;
    const int tid = threadIdx.x;
    const int lrow = tid >> 1, lcol = (tid & 1) * 4;
    const int tx = tid & 15, ty = tid >> 4;

    const float* Qp = Q + (size_t)(b * Lseq + m0 + lrow) * Dm + h * DKh + lcol;
    const float* Kp = Km + (size_t)(b * Lseq + n0 + lrow) * Dm + h * DKh + lcol;

    float acc[8][8];
#pragma unroll
    for (int i = 0; i < 8; i++)
#pragma unroll
        for (int j = 0; j < 8; j++) acc[i][j] = 0.f;

    for (int k0 = 0; k0 < DKh; k0 += 8) {
        float4 qv = *(const float4*)(Qp + k0);
        float4 kv = *(const float4*)(Kp + k0);
        Qs[lcol + 0][lrow] = qv.x; Qs[lcol + 1][lrow] = qv.y;
        Qs[lcol + 2][lrow] = qv.z; Qs[lcol + 3][lrow] = qv.w;
        Ks[lcol + 0][lrow] = kv.x; Ks[lcol + 1][lrow] = kv.y;
        Ks[lcol + 2][lrow] = kv.z; Ks[lcol + 3][lrow] = kv.w;
        __syncthreads();
#pragma unroll
        for (int kk = 0; kk < 8; kk++) {
            float a[8], w[8];
#pragma unroll
            for (int i = 0; i < 8; i++) a[i] = Qs[kk][ty * 8 + i];
#pragma unroll
            for (int j = 0; j < 8; j++) w[j] = Ks[kk][tx * 8 + j];
#pragma unroll
            for (int i = 0; i < 8; i++)
#pragma unroll
                for (int j = 0; j < 8; j++)
                    acc[i][j] = fmaf(a[i], w[j], acc[i][j]);
        }
        __syncthreads();
    }

    bool km[8];
#pragma unroll
    for (int j = 0; j < 8; j++)
        km[j] = (mask[b * Lseq + n0 + tx * 8 + j] == 0);

    float* abase = attn + (size_t)bh * Lseq * Lseq;
#pragma unroll
    for (int i = 0; i < 8; i++) {
        const int qq = m0 + ty * 8 + i;
        const float* pr = prior + ((size_t)b * Lseq + qq) * Lseq;
        float* arow = abase + (size_t)qq * Lseq;
#pragma unroll
        for (int j = 0; j < 8; j++) {
            const int kk = n0 + tx * 8 + j;
            arow[kk] = km[j] ? -1e9f : acc[i][j] * pr[kk];
        }
    }
}

// ---------------- Row softmax over 2048, in place ----------------
__global__ __launch_bounds__(256) void softmax_kernel(float* __restrict__ attn)
{
    __shared__ float red[256];
    float* row = attn + (size_t)blockIdx.x * Lseq;
    const int tid = threadIdx.x;
    float4 v0 = ((const float4*)row)[tid];
    float4 v1 = ((const float4*)row)[tid + 256];

    float m = fmaxf(fmaxf(fmaxf(v0.x, v0.y), fmaxf(v0.z, v0.w)),
                    fmaxf(fmaxf(v1.x, v1.y), fmaxf(v1.z, v1.w)));
    red[tid] = m;
    __syncthreads();
    for (int o = 128; o > 0; o >>= 1) {
        if (tid < o) red[tid] = fmaxf(red[tid], red[tid + o]);
        __syncthreads();
    }
    const float rmax = red[0];
    __syncthreads();

    v0.x = expf(v0.x - rmax); v0.y = expf(v0.y - rmax);
    v0.z = expf(v0.z - rmax); v0.w = expf(v0.w - rmax);
    v1.x = expf(v1.x - rmax); v1.y = expf(v1.y - rmax);
    v1.z = expf(v1.z - rmax); v1.w = expf(v1.w - rmax);

    red[tid] = v0.x + v0.y + v0.z + v0.w + v1.x + v1.y + v1.z + v1.w;
    __syncthreads();
    for (int o = 128; o > 0; o >>= 1) {
        if (tid < o) red[tid] += red[tid + o];
        __syncthreads();
    }
    const float inv = 1.0f / red[0];

    v0.x *= inv; v0.y *= inv; v0.z *= inv; v0.w *= inv;
    v1.x *= inv; v1.y *= inv; v1.z *= inv; v1.w *= inv;
    ((float4*)row)[tid] = v0;
    ((float4*)row)[tid + 256] = v1;
}

// ---------------- AV: O[b,q,h*64+d] = sum_k attn[b,h,q,k] * V[b,k,h*64+d] ----------------
// BM=128 (q), BN=64 (d), BK=16, 256 threads, 8x4 per thread.
__global__ __launch_bounds__(256) void av_kernel(const float* __restrict__ attn,
                                                 const float* __restrict__ V,
                                                 float* __restrict__ O)
{
    __shared__ float Ss[16][128];
    __shared__ float Vs[16][64];
    const int bh = blockIdx.z, b = bh >> 4, h = bh & 15;
    const int m0 = blockIdx.y * 128;
    const int tid = threadIdx.x;

    const float* Sbase = attn + (size_t)bh * Lseq * Lseq;
    const int ar = tid >> 1;            // 0..127
    const int ac = (tid & 1) * 8;       // 0 or 8
    const int vr = tid >> 4;            // 0..15
    const int vc = (tid & 15) * 4;      // 0..60
    const int tx = tid & 15, ty = tid >> 4;

    float acc[8][4];
#pragma unroll
    for (int i = 0; i < 8; i++)
#pragma unroll
        for (int j = 0; j < 4; j++) acc[i][j] = 0.f;

    const float* Sp = Sbase + (size_t)(m0 + ar) * Lseq + ac;
    const float* Vp = V + (size_t)(b * Lseq + vr) * Dm + h * DKh + vc;

    for (int k0 = 0; k0 < Lseq; k0 += 16) {
        float4 s0 = *(const float4*)(Sp + k0);
        float4 s1 = *(const float4*)(Sp + k0 + 4);
        Ss[ac + 0][ar] = s0.x; Ss[ac + 1][ar] = s0.y;
        Ss[ac + 2][ar] = s0.z; Ss[ac + 3][ar] = s0.w;
        Ss[ac + 4][ar] = s1.x; Ss[ac + 5][ar] = s1.y;
        Ss[ac + 6][ar] = s1.z; Ss[ac + 7][ar] = s1.w;
        float4 vv = *(const float4*)(Vp + (size_t)k0 * Dm);
        *(float4*)&Vs[vr][vc] = vv;
        __syncthreads();
#pragma unroll
        for (int kk = 0; kk < 16; kk++) {
            float a[8], w[4];
#pragma unroll
            for (int i = 0; i < 8; i++) a[i] = Ss[kk][ty * 8 + i];
#pragma unroll
            for (int j = 0; j < 4; j++) w[j] = Vs[kk][tx * 4 + j];
#pragma unroll
            for (int i = 0; i < 8; i++)
#pragma unroll
                for (int j = 0; j < 4; j++)
                    acc[i][j] = fmaf(a[i], w[j], acc[i][j]);
        }
        __syncthreads();
    }

#pragma unroll
    for (int i = 0; i < 8; i++) {
        float* orow = O + (size_t)(b * Lseq + m0 + ty * 8 + i) * Dm + h * DKh + tx * 4;
        float4 o4 = make_float4(acc[i][0], acc[i][1], acc[i][2], acc[i][3]);
        *(float4*)orow = o4;
    }
}

// ---------------- launch ----------------
extern "C" void kernel_launch(void* const* d_in, const int* in_sizes, int n_in,
                              void* d_out, int out_size)
{
    const float* src   = (const float*)d_in[0];
    const int*   mask  = (const int*)d_in[1];
    const float* prior = (const float*)d_in[2];
    const float* ln1_g = (const float*)d_in[3];
    const float* ln1_b = (const float*)d_in[4];
    const float* wq    = (const float*)d_in[5];
    const float* wk    = (const float*)d_in[6];
    const float* wv    = (const float*)d_in[7];
    const float* fc_w  = (const float*)d_in[8];
    const float* ln2_g = (const float*)d_in[9];
    const float* ln2_b = (const float*)d_in[10];
    const float* w1_w  = (const float*)d_in[11];
    const float* w1_b  = (const float*)d_in[12];
    const float* w2_w  = (const float*)d_in[13];
    const float* w2_b  = (const float*)d_in[14];

    float* out_y    = (float*)d_out;                       // [B,L,D]
    float* out_attn = out_y + (size_t)NTOK * Dm;           // [B,H,L,L]

    float *x, *q, *k, *v, *o, *y, *z, *hb;
    cudaGetSymbolAddress((void**)&x,  g_x);
    cudaGetSymbolAddress((void**)&q,  g_q);
    cudaGetSymbolAddress((void**)&k,  g_k);
    cudaGetSymbolAddress((void**)&v,  g_v);
    cudaGetSymbolAddress((void**)&o,  g_o);
    cudaGetSymbolAddress((void**)&y,  g_y);
    cudaGetSymbolAddress((void**)&z,  g_z);
    cudaGetSymbolAddress((void**)&hb, g_h);

    // 1) pre-LN
    ln_kernel<<<NTOK, 256>>>(src, ln1_g, ln1_b, x);

    // 2) QKV projections (Q pre-scaled by 1/sqrt(dk) = 0.125)
    dim3 gD(Dm / 128, NTOK / 128);
    gemm_nt<0><<<gD, 256>>>(x, wq, q, NTOK, Dm, Dm, nullptr, nullptr, 0.125f);
    gemm_nt<0><<<gD, 256>>>(x, wk, k, NTOK, Dm, Dm, nullptr, nullptr, 1.0f);
    gemm_nt<0><<<gD, 256>>>(x, wv, v, NTOK, Dm, Dm, nullptr, nullptr, 1.0f);

    // 3) scores + prior + mask -> attn output region
    dim3 gS(Lseq / 128, Lseq / 128, Bsz * Hn);
    scores_kernel<<<gS, 256>>>(q, k, prior, mask, out_attn);

    // 4) softmax in place (this IS the second output)
    softmax_kernel<<<Bsz * Hn * Lseq, 256>>>(out_attn);

    // 5) O = attn @ V
    dim3 gAV(1, Lseq / 128, Bsz * Hn);
    av_kernel<<<gAV, 256>>>(out_attn, v, o);

    // 6) y = O @ fc^T + src
    gemm_nt<1><<<gD, 256>>>(o, fc_w, y, NTOK, Dm, Dm, nullptr, src, 1.0f);

    // 7) FFN: z = LN(y); h = relu(z@w1^T + b1); out_y = h@w2^T + b2 + y
    ln_kernel<<<NTOK, 256>>>(y, ln2_g, ln2_b, z);
    dim3 gF(DFFn / 128, NTOK / 128);
    gemm_nt<2><<<gF, 256>>>(z, w1_w, hb, NTOK, DFFn, Dm, w1_b, nullptr, 1.0f);
    gemm_nt<3><<<gD, 256>>>(hb, w2_w, out_y, NTOK, Dm, DFFn, w2_b, y, 1.0f);
}

// round 4
// speedup vs baseline: 1.0009x; 1.0009x over previous
#include <cuda_runtime.h>
#include <math.h>

// Problem dims (fixed)
#define Bsz  4
#define Lseq 2048
#define Dm   1024
#define Hn   16
#define DKh  64
#define DFFn 4096
#define NTOK (Bsz * Lseq)   // 8192

// ---------------- scratch (no cudaMalloc allowed) ----------------
__device__ float g_x[(size_t)NTOK * Dm];
__device__ float g_q[(size_t)NTOK * Dm];
__device__ float g_k[(size_t)NTOK * Dm];
__device__ float g_v[(size_t)NTOK * Dm];
__device__ float g_o[(size_t)NTOK * Dm];
__device__ float g_y[(size_t)NTOK * Dm];
__device__ float g_z[(size_t)NTOK * Dm];
__device__ float g_h[(size_t)NTOK * DFFn];

// ---------------- LayerNorm: one block (256 thr) per row of 1024 ----------------
__global__ __launch_bounds__(256) void ln_kernel(const float* __restrict__ x,
                                                 const float* __restrict__ g,
                                                 const float* __restrict__ b,
                                                 float* __restrict__ out)
{
    __shared__ float red[256];
    const size_t row = blockIdx.x;
    const int tid = threadIdx.x;
    float4 v = ((const float4*)(x + row * Dm))[tid];

    red[tid] = v.x + v.y + v.z + v.w;
    __syncthreads();
    for (int o = 128; o > 0; o >>= 1) {
        if (tid < o) red[tid] += red[tid + o];
        __syncthreads();
    }
    const float mu = red[0] * (1.0f / Dm);
    __syncthreads();

    const float dx = v.x - mu, dy = v.y - mu, dz = v.z - mu, dw = v.w - mu;
    red[tid] = dx * dx + dy * dy + dz * dz + dw * dw;
    __syncthreads();
    for (int o = 128; o > 0; o >>= 1) {
        if (tid < o) red[tid] += red[tid + o];
        __syncthreads();
    }
    const float inv = rsqrtf(red[0] * (1.0f / Dm) + 1e-6f);

    const float4 gg = ((const float4*)g)[tid];
    const float4 bb = ((const float4*)b)[tid];
    float4 o4;
    o4.x = dx * inv * gg.x + bb.x;
    o4.y = dy * inv * gg.y + bb.y;
    o4.z = dz * inv * gg.z + bb.z;
    o4.w = dw * inv * gg.w + bb.w;
    ((float4*)(out + row * Dm))[tid] = o4;
}

// ---------------- Generic NT GEMM: C[M,N] = A[M,K] @ W[N,K]^T (+ epilogue) ----------------
// 128x128 tile, BK=8, 256 threads, 8x8 per thread.
// EPI: 0 = alpha*acc ; 1 = acc + resid ; 2 = relu(acc + bias[n]) ; 3 = acc + bias[n] + resid
template <int EPI>
__global__ __launch_bounds__(256) void gemm_nt(const float* __restrict__ A,
                                               const float* __restrict__ W,
                                               float* __restrict__ C,
                                               int M, int N, int K,
                                               const float* __restrict__ bias,
                                               const float* __restrict__ resid,
                                               float alpha)
{
    __shared__ float As[8][128];
    __shared__ float Ws[8][128];
    const int tid = threadIdx.x;
    const int m0 = blockIdx.y * 128;
    const int n0 = blockIdx.x * 128;
    const int lrow = tid >> 1;          // 0..127
    const int lcol = (tid & 1) * 4;     // 0 or 4
    const int tx = tid & 15, ty = tid >> 4;

    const float* Ap = A + (size_t)(m0 + lrow) * K + lcol;
    const float* Wp = W + (size_t)(n0 + lrow) * K + lcol;

    float acc[8][8];
#pragma unroll
    for (int i = 0; i < 8; i++)
#pragma unroll
        for (int j = 0; j < 8; j++) acc[i][j] = 0.f;

    for (int k0 = 0; k0 < K; k0 += 8) {
        float4 av = *(const float4*)(Ap + k0);
        float4 wv = *(const float4*)(Wp + k0);
        As[lcol + 0][lrow] = av.x; As[lcol + 1][lrow] = av.y;
        As[lcol + 2][lrow] = av.z; As[lcol + 3][lrow] = av.w;
        Ws[lcol + 0][lrow] = wv.x; Ws[lcol + 1][lrow] = wv.y;
        Ws[lcol + 2][lrow] = wv.z; Ws[lcol + 3][lrow] = wv.w;
        __syncthreads();
#pragma unroll
        for (int kk = 0; kk < 8; kk++) {
            float a[8], w[8];
#pragma unroll
            for (int i = 0; i < 8; i++) a[i] = As[kk][ty * 8 + i];
#pragma unroll
            for (int j = 0; j < 8; j++) w[j] = Ws[kk][tx * 8 + j];
#pragma unroll
            for (int i = 0; i < 8; i++)
#pragma unroll
                for (int j = 0; j < 8; j++)
                    acc[i][j] = fmaf(a[i], w[j], acc[i][j]);
        }
        __syncthreads();
    }

#pragma unroll
    for (int i = 0; i < 8; i++) {
        const int m = m0 + ty * 8 + i;
#pragma unroll
        for (int j = 0; j < 8; j++) {
            const int n = n0 + tx * 8 + j;
            float v = acc[i][j];
            if (EPI == 0)      v *= alpha;
            else if (EPI == 1) v += resid[(size_t)m * N + n];
            else if (EPI == 2) v = fmaxf(v + bias[n], 0.f);
            else if (EPI == 3) v += bias[n] + resid[(size_t)m * N + n];
            C[(size_t)m * N + n] = v;
        }
    }
}

// ---------------- Scores: S[b,h,q,k] = (Q/8 . K) * prior[b,q,k] ; masked -> -1e9 ----------------
// Q is pre-scaled by 1/8 in its projection epilogue.
__global__ __launch_bounds__(256) void scores_kernel(const float* __restrict__ Q,
                                                     const float* __restrict__ Km,
                                                     const float* __restrict__ prior,
                                                     const int* __restrict__ mask,
                                                     float* __restrict__ attn)
{
    __shared__ float Qs[8][128];
    __shared__ float Ks[8][128];
    const int bh = blockIdx.z, b = bh >> 4, h = bh & 15;
    const int m0 = blockIdx.y * 128, n0 = blockIdx.x * 128;
    const int tid = threadIdx.x;
    const int lrow = tid >> 1, lcol = (tid & 1) * 4;
    const int tx = tid & 15, ty = tid >> 4;

    const float* Qp = Q + (size_t)(b * Lseq + m0 + lrow) * Dm + h * DKh + lcol;
    const float* Kp = Km + (size_t)(b * Lseq + n0 + lrow) * Dm + h * DKh + lcol;

    float acc[8][8];
#pragma unroll
    for (int i = 0; i < 8; i++)
#pragma unroll
        for (int j = 0; j < 8; j++) acc[i][j] = 0.f;

    for (int k0 = 0; k0 < DKh; k0 += 8) {
        float4 qv = *(const float4*)(Qp + k0);
        float4 kv = *(const float4*)(Kp + k0);
        Qs[lcol + 0][lrow] = qv.x; Qs[lcol + 1][lrow] = qv.y;
        Qs[lcol + 2][lrow] = qv.z; Qs[lcol + 3][lrow] = qv.w;
        Ks[lcol + 0][lrow] = kv.x; Ks[lcol + 1][lrow] = kv.y;
        Ks[lcol + 2][lrow] = kv.z; Ks[lcol + 3][lrow] = kv.w;
        __syncthreads();
#pragma unroll
        for (int kk = 0; kk < 8; kk++) {
            float a[8], w[8];
#pragma unroll
            for (int i = 0; i < 8; i++) a[i] = Qs[kk][ty * 8 + i];
#pragma unroll
            for (int j = 0; j < 8; j++) w[j] = Ks[kk][tx * 8 + j];
#pragma unroll
            for (int i = 0; i < 8; i++)
#pragma unroll
                for (int j = 0; j < 8; j++)
                    acc[i][j] = fmaf(a[i], w[j], acc[i][j]);
        }
        __syncthreads();
    }

    bool km[8];
#pragma unroll
    for (int j = 0; j < 8; j++)
        km[j] = (mask[b * Lseq + n0 + tx * 8 + j] == 0);

    float* abase = attn + (size_t)bh * Lseq * Lseq;
#pragma unroll
    for (int i = 0; i < 8; i++) {
        const int qq = m0 + ty * 8 + i;
        const float* pr = prior + ((size_t)b * Lseq + qq) * Lseq;
        float* arow = abase + (size_t)qq * Lseq;
#pragma unroll
        for (int j = 0; j < 8; j++) {
            const int kk = n0 + tx * 8 + j;
            arow[kk] = km[j] ? -1e9f : acc[i][j] * pr[kk];
        }
    }
}

// ---------------- Row softmax over 2048, in place ----------------
__global__ __launch_bounds__(256) void softmax_kernel(float* __restrict__ attn)
{
    __shared__ float red[256];
    float* row = attn + (size_t)blockIdx.x * Lseq;
    const int tid = threadIdx.x;
    float4 v0 = ((const float4*)row)[tid];
    float4 v1 = ((const float4*)row)[tid + 256];

    float m = fmaxf(fmaxf(fmaxf(v0.x, v0.y), fmaxf(v0.z, v0.w)),
                    fmaxf(fmaxf(v1.x, v1.y), fmaxf(v1.z, v1.w)));
    red[tid] = m;
    __syncthreads();
    for (int o = 128; o > 0; o >>= 1) {
        if (tid < o) red[tid] = fmaxf(red[tid], red[tid + o]);
        __syncthreads();
    }
    const float rmax = red[0];
    __syncthreads();

    v0.x = expf(v0.x - rmax); v0.y = expf(v0.y - rmax);
    v0.z = expf(v0.z - rmax); v0.w = expf(v0.w - rmax);
    v1.x = expf(v1.x - rmax); v1.y = expf(v1.y - rmax);
    v1.z = expf(v1.z - rmax); v1.w = expf(v1.w - rmax);

    red[tid] = v0.x + v0.y + v0.z + v0.w + v1.x + v1.y + v1.z + v1.w;
    __syncthreads();
    for (int o = 128; o > 0; o >>= 1) {
        if (tid < o) red[tid] += red[tid + o];
        __syncthreads();
    }
    const float inv = 1.0f / red[0];

    v0.x *= inv; v0.y *= inv; v0.z *= inv; v0.w *= inv;
    v1.x *= inv; v1.y *= inv; v1.z *= inv; v1.w *= inv;
    ((float4*)row)[tid] = v0;
    ((float4*)row)[tid + 256] = v1;
}

// ---------------- AV: O[b,q,h*64+d] = sum_k attn[b,h,q,k] * V[b,k,h*64+d] ----------------
// BM=128 (q), BN=64 (d), BK=16, 256 threads, 8x4 per thread.
__global__ __launch_bounds__(256) void av_kernel(const float* __restrict__ attn,
                                                 const float* __restrict__ V,
                                                 float* __restrict__ O)
{
    __shared__ float Ss[16][128];
    __shared__ float Vs[16][64];
    const int bh = blockIdx.z, b = bh >> 4, h = bh & 15;
    const int m0 = blockIdx.y * 128;
    const int tid = threadIdx.x;

    const float* Sbase = attn + (size_t)bh * Lseq * Lseq;
    const int ar = tid >> 1;            // 0..127
    const int ac = (tid & 1) * 8;       // 0 or 8
    const int vr = tid >> 4;            // 0..15
    const int vc = (tid & 15) * 4;      // 0..60
    const int tx = tid & 15, ty = tid >> 4;

    float acc[8][4];
#pragma unroll
    for (int i = 0; i < 8; i++)
#pragma unroll
        for (int j = 0; j < 4; j++) acc[i][j] = 0.f;

    const float* Sp = Sbase + (size_t)(m0 + ar) * Lseq + ac;
    const float* Vp = V + (size_t)(b * Lseq + vr) * Dm + h * DKh + vc;

    for (int k0 = 0; k0 < Lseq; k0 += 16) {
        float4 s0 = *(const float4*)(Sp + k0);
        float4 s1 = *(const float4*)(Sp + k0 + 4);
        Ss[ac + 0][ar] = s0.x; Ss[ac + 1][ar] = s0.y;
        Ss[ac + 2][ar] = s0.z; Ss[ac + 3][ar] = s0.w;
        Ss[ac + 4][ar] = s1.x; Ss[ac + 5][ar] = s1.y;
        Ss[ac + 6][ar] = s1.z; Ss[ac + 7][ar] = s1.w;
        float4 vv = *(const float4*)(Vp + (size_t)k0 * Dm);
        *(float4*)&Vs[vr][vc] = vv;
        __syncthreads();
#pragma unroll
        for (int kk = 0; kk < 16; kk++) {
            float a[8], w[4];
#pragma unroll
            for (int i = 0; i < 8; i++) a[i] = Ss[kk][ty * 8 + i];
#pragma unroll
            for (int j = 0; j < 4; j++) w[j] = Vs[kk][tx * 4 + j];
#pragma unroll
            for (int i = 0; i < 8; i++)
#pragma unroll
                for (int j = 0; j < 4; j++)
                    acc[i][j] = fmaf(a[i], w[j], acc[i][j]);
        }
        __syncthreads();
    }

#pragma unroll
    for (int i = 0; i < 8; i++) {
        float* orow = O + (size_t)(b * Lseq + m0 + ty * 8 + i) * Dm + h * DKh + tx * 4;
        float4 o4 = make_float4(acc[i][0], acc[i][1], acc[i][2], acc[i][3]);
        *(float4*)orow = o4;
    }
}

// ---------------- launch ----------------
extern "C" void kernel_launch(void* const* d_in, const int* in_sizes, int n_in,
                              void* d_out, int out_size)
{
    const float* src   = (const float*)d_in[0];
    const int*   mask  = (const int*)d_in[1];
    const float* prior = (const float*)d_in[2];
    const float* ln1_g = (const float*)d_in[3];
    const float* ln1_b = (const float*)d_in[4];
    const float* wq    = (const float*)d_in[5];
    const float* wk    = (const float*)d_in[6];
    const float* wv    = (const float*)d_in[7];
    const float* fc_w  = (const float*)d_in[8];
    const float* ln2_g = (const float*)d_in[9];
    const float* ln2_b = (const float*)d_in[10];
    const float* w1_w  = (const float*)d_in[11];
    const float* w1_b  = (const float*)d_in[12];
    const float* w2_w  = (const float*)d_in[13];
    const float* w2_b  = (const float*)d_in[14];

    float* out_y    = (float*)d_out;                       // [B,L,D]
    float* out_attn = out_y + (size_t)NTOK * Dm;           // [B,H,L,L]

    float *x, *q, *k, *v, *o, *y, *z, *hb;
    cudaGetSymbolAddress((void**)&x,  g_x);
    cudaGetSymbolAddress((void**)&q,  g_q);
    cudaGetSymbolAddress((void**)&k,  g_k);
    cudaGetSymbolAddress((void**)&v,  g_v);
    cudaGetSymbolAddress((void**)&o,  g_o);
    cudaGetSymbolAddress((void**)&y,  g_y);
    cudaGetSymbolAddress((void**)&z,  g_z);
    cudaGetSymbolAddress((void**)&hb, g_h);

    // 1) pre-LN
    ln_kernel<<<NTOK, 256>>>(src, ln1_g, ln1_b, x);

    // 2) QKV projections (Q pre-scaled by 1/sqrt(dk) = 0.125)
    dim3 gD(Dm / 128, NTOK / 128);
    gemm_nt<0><<<gD, 256>>>(x, wq, q, NTOK, Dm, Dm, nullptr, nullptr, 0.125f);
    gemm_nt<0><<<gD, 256>>>(x, wk, k, NTOK, Dm, Dm, nullptr, nullptr, 1.0f);
    gemm_nt<0><<<gD, 256>>>(x, wv, v, NTOK, Dm, Dm, nullptr, nullptr, 1.0f);

    // 3) scores + prior + mask -> attn output region
    dim3 gS(Lseq / 128, Lseq / 128, Bsz * Hn);
    scores_kernel<<<gS, 256>>>(q, k, prior, mask, out_attn);

    // 4) softmax in place (this IS the second output)
    softmax_kernel<<<Bsz * Hn * Lseq, 256>>>(out_attn);

    // 5) O = attn @ V
    dim3 gAV(1, Lseq / 128, Bsz * Hn);
    av_kernel<<<gAV, 256>>>(out_attn, v, o);

    // 6) y = O @ fc^T + src
    gemm_nt<1><<<gD, 256>>>(o, fc_w, y, NTOK, Dm, Dm, nullptr, src, 1.0f);

    // 7) FFN: z = LN(y); h = relu(z@w1^T + b1); out_y = h@w2^T + b2 + y
    ln_kernel<<<NTOK, 256>>>(y, ln2_g, ln2_b, z);
    dim3 gF(DFFn / 128, NTOK / 128);
    gemm_nt<2><<<gF, 256>>>(z, w1_w, hb, NTOK, DFFn, Dm, w1_b, nullptr, 1.0f);
    gemm_nt<3><<<gD, 256>>>(hb, w2_w, out_y, NTOK, Dm, DFFn, w2_b, y, 1.0f);
}

// round 5
// speedup vs baseline: 2.2716x; 2.2695x over previous
#include <cuda_runtime.h>
#include <math.h>
#include <stdint.h>

// Problem dims (fixed)
#define Bsz  4
#define Lseq 2048
#define Dm   1024
#define Hn   16
#define DKh  64
#define DFFn 4096
#define NTOK (Bsz * Lseq)   // 8192

// ---------------- scratch (no cudaMalloc allowed) ----------------
__device__ float g_x[(size_t)NTOK * Dm];
__device__ float g_q[(size_t)NTOK * Dm];
__device__ float g_k[(size_t)NTOK * Dm];
__device__ float g_v[(size_t)NTOK * Dm];
__device__ float g_o[(size_t)NTOK * Dm];
__device__ float g_y[(size_t)NTOK * Dm];
__device__ float g_z[(size_t)NTOK * Dm];
__device__ float g_h[(size_t)NTOK * DFFn];
// tf32-rounded weight copies
__device__ float g_wq[(size_t)Dm * Dm];
__device__ float g_wk[(size_t)Dm * Dm];
__device__ float g_wv[(size_t)Dm * Dm];
__device__ float g_fc[(size_t)Dm * Dm];
__device__ float g_w1[(size_t)DFFn * Dm];
__device__ float g_w2[(size_t)Dm * DFFn];

// ---------------- helpers ----------------
__device__ __forceinline__ float rtf32(float x) {
    uint32_t u;
    asm("cvt.rna.tf32.f32 %0, %1;" : "=r"(u) : "f"(x));
    return __uint_as_float(u);
}

__device__ __forceinline__ void mma_tf32(float c[4], const uint32_t a[4], const uint32_t b[2]) {
    asm volatile(
        "mma.sync.aligned.m16n8k8.row.col.f32.tf32.tf32.f32 "
        "{%0,%1,%2,%3}, {%4,%5,%6,%7}, {%8,%9}, {%0,%1,%2,%3};\n"
        : "+f"(c[0]), "+f"(c[1]), "+f"(c[2]), "+f"(c[3])
        : "r"(a[0]), "r"(a[1]), "r"(a[2]), "r"(a[3]), "r"(b[0]), "r"(b[1]));
}

#define CP16(dst, src) asm volatile("cp.async.ca.shared.global [%0], [%1], 16;\n" :: "r"(dst), "l"(src))
#define CP_COMMIT() asm volatile("cp.async.commit_group;\n")
#define CP_WAIT1()  asm volatile("cp.async.wait_group 1;\n")

// ---------------- tf32 rounding copy (weights prep) ----------------
__global__ __launch_bounds__(256) void round_copy_kernel(const float* __restrict__ in,
                                                         float* __restrict__ out, int n4)
{
    int i = blockIdx.x * blockDim.x + threadIdx.x;
    int stride = gridDim.x * blockDim.x;
    for (; i < n4; i += stride) {
        float4 v = ((const float4*)in)[i];
        v.x = rtf32(v.x); v.y = rtf32(v.y); v.z = rtf32(v.z); v.w = rtf32(v.w);
        ((float4*)out)[i] = v;
    }
}

// ---------------- LayerNorm: one block (256 thr) per row of 1024 ----------------
template <bool ROUND>
__global__ __launch_bounds__(256) void ln_kernel(const float* __restrict__ x,
                                                 const float* __restrict__ g,
                                                 const float* __restrict__ b,
                                                 float* __restrict__ out)
{
    __shared__ float red[256];
    const size_t row = blockIdx.x;
    const int tid = threadIdx.x;
    float4 v = ((const float4*)(x + row * Dm))[tid];

    red[tid] = v.x + v.y + v.z + v.w;
    __syncthreads();
    for (int o = 128; o > 0; o >>= 1) {
        if (tid < o) red[tid] += red[tid + o];
        __syncthreads();
    }
    const float mu = red[0] * (1.0f / Dm);
    __syncthreads();

    const float dx = v.x - mu, dy = v.y - mu, dz = v.z - mu, dw = v.w - mu;
    red[tid] = dx * dx + dy * dy + dz * dz + dw * dw;
    __syncthreads();
    for (int o = 128; o > 0; o >>= 1) {
        if (tid < o) red[tid] += red[tid + o];
        __syncthreads();
    }
    const float inv = rsqrtf(red[0] * (1.0f / Dm) + 1e-6f);

    const float4 gg = ((const float4*)g)[tid];
    const float4 bb = ((const float4*)b)[tid];
    float4 o4;
    o4.x = dx * inv * gg.x + bb.x;
    o4.y = dy * inv * gg.y + bb.y;
    o4.z = dz * inv * gg.z + bb.z;
    o4.w = dw * inv * gg.w + bb.w;
    if (ROUND) {
        o4.x = rtf32(o4.x); o4.y = rtf32(o4.y); o4.z = rtf32(o4.z); o4.w = rtf32(o4.w);
    }
    ((float4*)(out + row * Dm))[tid] = o4;
}

// ============================================================================
// Tensor-core NT GEMM: C[M,N] = A[M,K] @ W[N,K]^T  (A, W pre-rounded to tf32)
// BM=128, BN=128, BK=16, 256 threads (8 warps: 4M x 2N), warp tile 32x64.
// Double-buffered cp.async. EPI: 0=alpha*acc ; 1=acc+resid ; 2=relu(acc+bias) ;
// 3=acc+bias+resid. ROUND: cvt.rna.tf32 on output.
// ============================================================================
#define GS 20   // smem row stride (16 + 4 pad)
template <int EPI, bool ROUND>
__global__ __launch_bounds__(256) void gemm_tc(const float* __restrict__ A,
                                               const float* __restrict__ W,
                                               float* __restrict__ C,
                                               int M, int N, int K,
                                               const float* __restrict__ bias,
                                               const float* __restrict__ resid,
                                               float alpha)
{
    __shared__ float As[2][128 * GS];
    __shared__ float Bs[2][128 * GS];
    const int tid  = threadIdx.x;
    const int lane = tid & 31;
    const int warp = tid >> 5;
    const int wm = warp >> 1;      // 0..3
    const int wn = warp & 1;       // 0..1
    const int m0 = blockIdx.y * 128;
    const int n0 = blockIdx.x * 128;

    const int lrow = tid >> 1;           // 0..127
    const int lkc  = (tid & 1) * 8;      // 0 or 8
    const float* Ag = A + (size_t)(m0 + lrow) * K + lkc;
    const float* Wg = W + (size_t)(n0 + lrow) * K + lkc;
    const uint32_t sA = (uint32_t)__cvta_generic_to_shared(&As[0][0]);
    const uint32_t sB = (uint32_t)__cvta_generic_to_shared(&Bs[0][0]);
    const uint32_t dOff = (lrow * GS + lkc) * 4;

    float acc[2][8][4];
#pragma unroll
    for (int i = 0; i < 2; i++)
#pragma unroll
        for (int j = 0; j < 8; j++)
#pragma unroll
            for (int t = 0; t < 4; t++) acc[i][j][t] = 0.f;

    const int nIter = K >> 4;

    // preload stage 0
    {
        uint32_t da = sA + dOff, db = sB + dOff;
        CP16(da, Ag); CP16(da + 16, Ag + 4);
        CP16(db, Wg); CP16(db + 16, Wg + 4);
    }
    CP_COMMIT();

    for (int it = 0; it < nIter; ++it) {
        const int s = it & 1;
        if (it + 1 < nIter) {
            const int s2 = (it + 1) & 1;
            const int k0 = (it + 1) << 4;
            uint32_t da = sA + s2 * (128 * GS * 4) + dOff;
            uint32_t db = sB + s2 * (128 * GS * 4) + dOff;
            CP16(da, Ag + k0); CP16(da + 16, Ag + k0 + 4);
            CP16(db, Wg + k0); CP16(db + 16, Wg + k0 + 4);
        }
        CP_COMMIT();
        CP_WAIT1();
        __syncthreads();

        const float* as = &As[s][0];
        const float* bs = &Bs[s][0];
#pragma unroll
        for (int ks = 0; ks < 2; ks++) {
            const int c = ks * 8 + (lane & 3);
            uint32_t af[2][4], bf[8][2];
#pragma unroll
            for (int mt = 0; mt < 2; mt++) {
                const int r = wm * 32 + mt * 16 + (lane >> 2);
                af[mt][0] = __float_as_uint(as[r * GS + c]);
                af[mt][1] = __float_as_uint(as[(r + 8) * GS + c]);
                af[mt][2] = __float_as_uint(as[r * GS + c + 4]);
                af[mt][3] = __float_as_uint(as[(r + 8) * GS + c + 4]);
            }
#pragma unroll
            for (int nt = 0; nt < 8; nt++) {
                const int n = wn * 64 + nt * 8 + (lane >> 2);
                bf[nt][0] = __float_as_uint(bs[n * GS + c]);
                bf[nt][1] = __float_as_uint(bs[n * GS + c + 4]);
            }
#pragma unroll
            for (int mt = 0; mt < 2; mt++)
#pragma unroll
                for (int nt = 0; nt < 8; nt++)
                    mma_tf32(acc[mt][nt], af[mt], bf[nt]);
        }
        __syncthreads();
    }

    // epilogue
#pragma unroll
    for (int mt = 0; mt < 2; mt++) {
#pragma unroll
        for (int nt = 0; nt < 8; nt++) {
            const int r = m0 + wm * 32 + mt * 16 + (lane >> 2);
            const int cidx = n0 + wn * 64 + nt * 8 + (lane & 3) * 2;
#pragma unroll
            for (int half = 0; half < 2; half++) {
                const int m = r + half * 8;
                float v0 = acc[mt][nt][half * 2 + 0];
                float v1 = acc[mt][nt][half * 2 + 1];
                if (EPI == 0)      { v0 *= alpha; v1 *= alpha; }
                else if (EPI == 1) {
                    const float* rp = resid + (size_t)m * N + cidx;
                    v0 += rp[0]; v1 += rp[1];
                }
                else if (EPI == 2) {
                    v0 = fmaxf(v0 + bias[cidx], 0.f);
                    v1 = fmaxf(v1 + bias[cidx + 1], 0.f);
                }
                else if (EPI == 3) {
                    const float* rp = resid + (size_t)m * N + cidx;
                    v0 += bias[cidx] + rp[0];
                    v1 += bias[cidx + 1] + rp[1];
                }
                if (ROUND) { v0 = rtf32(v0); v1 = rtf32(v1); }
                *(float2*)(C + (size_t)m * N + cidx) = make_float2(v0, v1);
            }
        }
    }
}

// ============================================================================
// Scores: S[b,h,q,k] = (Q/8 . K) * prior[b,q,k] ; masked -> -1e9
// BM=BN=128 over tokens, K=64 (2 iters of BK=32). Q pre-scaled & rounded.
// ============================================================================
#define SS 36  // smem stride 32+4
__global__ __launch_bounds__(256) void scores_tc(const float* __restrict__ Q,
                                                 const float* __restrict__ Km,
                                                 const float* __restrict__ prior,
                                                 const int* __restrict__ mask,
                                                 float* __restrict__ attn)
{
    __shared__ float Qs[128 * SS];
    __shared__ float Ks[128 * SS];
    const int bh = blockIdx.z, b = bh >> 4, h = bh & 15;
    const int m0 = blockIdx.y * 128, n0 = blockIdx.x * 128;
    const int tid = threadIdx.x;
    const int lane = tid & 31;
    const int warp = tid >> 5;
    const int wm = warp >> 1, wn = warp & 1;

    const int lrow = tid >> 1;
    const int lcg  = (tid & 1) * 16;
    const float* Qg = Q + (size_t)(b * Lseq + m0 + lrow) * Dm + h * DKh + lcg;
    const float* Kg = Km + (size_t)(b * Lseq + n0 + lrow) * Dm + h * DKh + lcg;

    float acc[2][8][4];
#pragma unroll
    for (int i = 0; i < 2; i++)
#pragma unroll
        for (int j = 0; j < 8; j++)
#pragma unroll
            for (int t = 0; t < 4; t++) acc[i][j][t] = 0.f;

#pragma unroll
    for (int it = 0; it < 2; it++) {
        const int k0 = it * 32;
#pragma unroll
        for (int j = 0; j < 4; j++) {
            float4 qv = *(const float4*)(Qg + k0 + 4 * j);
            float4 kv = *(const float4*)(Kg + k0 + 4 * j);
            *(float4*)&Qs[lrow * SS + lcg + 4 * j] = qv;
            *(float4*)&Ks[lrow * SS + lcg + 4 * j] = kv;
        }
        __syncthreads();
#pragma unroll
        for (int ks = 0; ks < 4; ks++) {
            const int c = ks * 8 + (lane & 3);
            uint32_t af[2][4], bf[8][2];
#pragma unroll
            for (int mt = 0; mt < 2; mt++) {
                const int r = wm * 32 + mt * 16 + (lane >> 2);
                af[mt][0] = __float_as_uint(Qs[r * SS + c]);
                af[mt][1] = __float_as_uint(Qs[(r + 8) * SS + c]);
                af[mt][2] = __float_as_uint(Qs[r * SS + c + 4]);
                af[mt][3] = __float_as_uint(Qs[(r + 8) * SS + c + 4]);
            }
#pragma unroll
            for (int nt = 0; nt < 8; nt++) {
                const int n = wn * 64 + nt * 8 + (lane >> 2);
                bf[nt][0] = __float_as_uint(Ks[n * SS + c]);
                bf[nt][1] = __float_as_uint(Ks[n * SS + c + 4]);
            }
#pragma unroll
            for (int mt = 0; mt < 2; mt++)
#pragma unroll
                for (int nt = 0; nt < 8; nt++)
                    mma_tf32(acc[mt][nt], af[mt], bf[nt]);
        }
        __syncthreads();
    }

    float* abase = attn + (size_t)bh * Lseq * Lseq;
#pragma unroll
    for (int mt = 0; mt < 2; mt++) {
#pragma unroll
        for (int nt = 0; nt < 8; nt++) {
            const int r = m0 + wm * 32 + mt * 16 + (lane >> 2);
            const int cidx = n0 + wn * 64 + nt * 8 + (lane & 3) * 2;
            const bool k0m = (mask[b * Lseq + cidx] == 0);
            const bool k1m = (mask[b * Lseq + cidx + 1] == 0);
#pragma unroll
            for (int half = 0; half < 2; half++) {
                const int q = r + half * 8;
                const float* pr = prior + ((size_t)b * Lseq + q) * Lseq + cidx;
                float v0 = k0m ? -1e9f : acc[mt][nt][half * 2 + 0] * pr[0];
                float v1 = k1m ? -1e9f : acc[mt][nt][half * 2 + 1] * pr[1];
                *(float2*)(abase + (size_t)q * Lseq + cidx) = make_float2(v0, v1);
            }
        }
    }
}

// ---------------- Row softmax over 2048, in place ----------------
__global__ __launch_bounds__(256) void softmax_kernel(float* __restrict__ attn)
{
    __shared__ float red[256];
    float* row = attn + (size_t)blockIdx.x * Lseq;
    const int tid = threadIdx.x;
    float4 v0 = ((const float4*)row)[tid];
    float4 v1 = ((const float4*)row)[tid + 256];

    float m = fmaxf(fmaxf(fmaxf(v0.x, v0.y), fmaxf(v0.z, v0.w)),
                    fmaxf(fmaxf(v1.x, v1.y), fmaxf(v1.z, v1.w)));
    red[tid] = m;
    __syncthreads();
    for (int o = 128; o > 0; o >>= 1) {
        if (tid < o) red[tid] = fmaxf(red[tid], red[tid + o]);
        __syncthreads();
    }
    const float rmax = red[0];
    __syncthreads();

    v0.x = expf(v0.x - rmax); v0.y = expf(v0.y - rmax);
    v0.z = expf(v0.z - rmax); v0.w = expf(v0.w - rmax);
    v1.x = expf(v1.x - rmax); v1.y = expf(v1.y - rmax);
    v1.z = expf(v1.z - rmax); v1.w = expf(v1.w - rmax);

    red[tid] = v0.x + v0.y + v0.z + v0.w + v1.x + v1.y + v1.z + v1.w;
    __syncthreads();
    for (int o = 128; o > 0; o >>= 1) {
        if (tid < o) red[tid] += red[tid + o];
        __syncthreads();
    }
    const float inv = 1.0f / red[0];

    v0.x *= inv; v0.y *= inv; v0.z *= inv; v0.w *= inv;
    v1.x *= inv; v1.y *= inv; v1.z *= inv; v1.w *= inv;
    ((float4*)row)[tid] = v0;
    ((float4*)row)[tid + 256] = v1;
}

// ============================================================================
// AV: O[b,q,h*64+d] = sum_k attn[b,h,q,k] * V[b,k,h*64+d]
// BM=128 (q), BN=64 (d), BK=32, 8 warps (4M x 2N), warp tile 32x32.
// attn rounded to tf32 in-register; V pre-rounded. Output rounded (feeds fc).
// ============================================================================
__global__ __launch_bounds__(256) void av_tc(const float* __restrict__ attn,
                                             const float* __restrict__ V,
                                             float* __restrict__ O)
{
    __shared__ float Ss[128 * SS];   // [q][k], stride 36
    __shared__ float Vs[64 * SS];    // [d][k], stride 36
    const int bh = blockIdx.z, b = bh >> 4, h = bh & 15;
    const int m0 = blockIdx.y * 128;
    const int tid = threadIdx.x;
    const int lane = tid & 31;
    const int warp = tid >> 5;
    const int wm = warp >> 1, wn = warp & 1;

    const int lrow = tid >> 1;
    const int lcg  = (tid & 1) * 16;
    const float* Sg = attn + (size_t)bh * Lseq * Lseq + (size_t)(m0 + lrow) * Lseq + lcg;
    // V transpose load: lane = k index, warp -> d group of 8
    const float* Vg = V + (size_t)((size_t)b * Lseq + lane) * Dm + h * DKh + warp * 8;

    float acc[2][4][4];
#pragma unroll
    for (int i = 0; i < 2; i++)
#pragma unroll
        for (int j = 0; j < 4; j++)
#pragma unroll
            for (int t = 0; t < 4; t++) acc[i][j][t] = 0.f;

    for (int k0 = 0; k0 < Lseq; k0 += 32) {
        // S tile: LDG + tf32 round + STS
#pragma unroll
        for (int j = 0; j < 4; j++) {
            float4 sv = *(const float4*)(Sg + k0 + 4 * j);
            sv.x = rtf32(sv.x); sv.y = rtf32(sv.y);
            sv.z = rtf32(sv.z); sv.w = rtf32(sv.w);
            *(float4*)&Ss[lrow * SS + lcg + 4 * j] = sv;
        }
        // V tile transpose: thread covers k=lane, d = warp*8 .. +7
        {
            const float* vp = Vg + (size_t)k0 * Dm;
            float4 a = *(const float4*)vp;
            float4 c = *(const float4*)(vp + 4);
            const int d0 = warp * 8;
            Vs[(d0 + 0) * SS + lane] = a.x;
            Vs[(d0 + 1) * SS + lane] = a.y;
            Vs[(d0 + 2) * SS + lane] = a.z;
            Vs[(d0 + 3) * SS + lane] = a.w;
            Vs[(d0 + 4) * SS + lane] = c.x;
            Vs[(d0 + 5) * SS + lane] = c.y;
            Vs[(d0 + 6) * SS + lane] = c.z;
            Vs[(d0 + 7) * SS + lane] = c.w;
        }
        __syncthreads();
#pragma unroll
        for (int ks = 0; ks < 4; ks++) {
            const int c = ks * 8 + (lane & 3);
            uint32_t af[2][4], bf[4][2];
#pragma unroll
            for (int mt = 0; mt < 2; mt++) {
                const int r = wm * 32 + mt * 16 + (lane >> 2);
                af[mt][0] = __float_as_uint(Ss[r * SS + c]);
                af[mt][1] = __float_as_uint(Ss[(r + 8) * SS + c]);
                af[mt][2] = __float_as_uint(Ss[r * SS + c + 4]);
                af[mt][3] = __float_as_uint(Ss[(r + 8) * SS + c + 4]);
            }
#pragma unroll
            for (int nt = 0; nt < 4; nt++) {
                const int n = wn * 32 + nt * 8 + (lane >> 2);
                bf[nt][0] = __float_as_uint(Vs[n * SS + c]);
                bf[nt][1] = __float_as_uint(Vs[n * SS + c + 4]);
            }
#pragma unroll
            for (int mt = 0; mt < 2; mt++)
#pragma unroll
                for (int nt = 0; nt < 4; nt++)
                    mma_tf32(acc[mt][nt], af[mt], bf[nt]);
        }
        __syncthreads();
    }

#pragma unroll
    for (int mt = 0; mt < 2; mt++) {
#pragma unroll
        for (int nt = 0; nt < 4; nt++) {
            const int r = m0 + wm * 32 + mt * 16 + (lane >> 2);
            const int d = wn * 32 + nt * 8 + (lane & 3) * 2;
#pragma unroll
            for (int half = 0; half < 2; half++) {
                const int q = r + half * 8;
                float v0 = rtf32(acc[mt][nt][half * 2 + 0]);
                float v1 = rtf32(acc[mt][nt][half * 2 + 1]);
                *(float2*)(O + (size_t)((size_t)b * Lseq + q) * Dm + h * DKh + d)
                    = make_float2(v0, v1);
            }
        }
    }
}

// ---------------- launch ----------------
extern "C" void kernel_launch(void* const* d_in, const int* in_sizes, int n_in,
                              void* d_out, int out_size)
{
    const float* src   = (const float*)d_in[0];
    const int*   mask  = (const int*)d_in[1];
    const float* prior = (const float*)d_in[2];
    const float* ln1_g = (const float*)d_in[3];
    const float* ln1_b = (const float*)d_in[4];
    const float* wq    = (const float*)d_in[5];
    const float* wk    = (const float*)d_in[6];
    const float* wv    = (const float*)d_in[7];
    const float* fc_w  = (const float*)d_in[8];
    const float* ln2_g = (const float*)d_in[9];
    const float* ln2_b = (const float*)d_in[10];
    const float* w1_w  = (const float*)d_in[11];
    const float* w1_b  = (const float*)d_in[12];
    const float* w2_w  = (const float*)d_in[13];
    const float* w2_b  = (const float*)d_in[14];

    float* out_y    = (float*)d_out;                       // [B,L,D]
    float* out_attn = out_y + (size_t)NTOK * Dm;           // [B,H,L,L]

    float *x, *q, *k, *v, *o, *y, *z, *hb;
    float *rwq, *rwk, *rwv, *rfc, *rw1, *rw2;
    cudaGetSymbolAddress((void**)&x,  g_x);
    cudaGetSymbolAddress((void**)&q,  g_q);
    cudaGetSymbolAddress((void**)&k,  g_k);
    cudaGetSymbolAddress((void**)&v,  g_v);
    cudaGetSymbolAddress((void**)&o,  g_o);
    cudaGetSymbolAddress((void**)&y,  g_y);
    cudaGetSymbolAddress((void**)&z,  g_z);
    cudaGetSymbolAddress((void**)&hb, g_h);
    cudaGetSymbolAddress((void**)&rwq, g_wq);
    cudaGetSymbolAddress((void**)&rwk, g_wk);
    cudaGetSymbolAddress((void**)&rwv, g_wv);
    cudaGetSymbolAddress((void**)&rfc, g_fc);
    cudaGetSymbolAddress((void**)&rw1, g_w1);
    cudaGetSymbolAddress((void**)&rw2, g_w2);

    // 0) tf32-round weight copies
    const int nD = (Dm * Dm) / 4, nF = (DFFn * Dm) / 4;
    round_copy_kernel<<<256, 256>>>(wq,   rwq, nD);
    round_copy_kernel<<<256, 256>>>(wk,   rwk, nD);
    round_copy_kernel<<<256, 256>>>(wv,   rwv, nD);
    round_copy_kernel<<<256, 256>>>(fc_w, rfc, nD);
    round_copy_kernel<<<512, 256>>>(w1_w, rw1, nF);
    round_copy_kernel<<<512, 256>>>(w2_w, rw2, nF);

    // 1) pre-LN (tf32-rounded output)
    ln_kernel<true><<<NTOK, 256>>>(src, ln1_g, ln1_b, x);

    // 2) QKV projections (Q pre-scaled by 1/8; outputs rounded for next GEMMs)
    dim3 gD(Dm / 128, NTOK / 128);
    gemm_tc<0, true><<<gD, 256>>>(x, rwq, q, NTOK, Dm, Dm, nullptr, nullptr, 0.125f);
    gemm_tc<0, true><<<gD, 256>>>(x, rwk, k, NTOK, Dm, Dm, nullptr, nullptr, 1.0f);
    gemm_tc<0, true><<<gD, 256>>>(x, rwv, v, NTOK, Dm, Dm, nullptr, nullptr, 1.0f);

    // 3) scores + prior + mask -> attn output region
    dim3 gS(Lseq / 128, Lseq / 128, Bsz * Hn);
    scores_tc<<<gS, 256>>>(q, k, prior, mask, out_attn);

    // 4) softmax in place (this IS the second output; stays fp32)
    softmax_kernel<<<Bsz * Hn * Lseq, 256>>>(out_attn);

    // 5) O = attn @ V (attn rounded in-register, O rounded)
    dim3 gAV(1, Lseq / 128, Bsz * Hn);
    av_tc<<<gAV, 256>>>(out_attn, v, o);

    // 6) y = O @ fc^T + src (exact fp32 epilogue)
    gemm_tc<1, false><<<gD, 256>>>(o, rfc, y, NTOK, Dm, Dm, nullptr, src, 1.0f);

    // 7) FFN: z = LN(y); h = relu(z@w1^T + b1); out_y = h@w2^T + b2 + y
    ln_kernel<true><<<NTOK, 256>>>(y, ln2_g, ln2_b, z);
    dim3 gF(DFFn / 128, NTOK / 128);
    gemm_tc<2, true><<<gF, 256>>>(z, rw1, hb, NTOK, DFFn, Dm, w1_b, nullptr, 1.0f);
    gemm_tc<3, false><<<gD, 256>>>(hb, rw2, out_y, NTOK, Dm, DFFn, w2_b, y, 1.0f);
}

// round 7
// speedup vs baseline: 2.6957x; 1.1867x over previous
#include <cuda_runtime.h>
#include <math.h>
#include <stdint.h>

// Problem dims (fixed)
#define Bsz  4
#define Lseq 2048
#define Dm   1024
#define Hn   16
#define DKh  64
#define DFFn 4096
#define NTOK (Bsz * Lseq)   // 8192
#define NROWS (Bsz * Hn * Lseq)  // 131072 attn rows

// ---------------- scratch (no cudaMalloc allowed) ----------------
__device__ float g_x[(size_t)NTOK * Dm];
__device__ float g_q[(size_t)NTOK * Dm];
__device__ float g_k[(size_t)NTOK * Dm];
__device__ float g_v[(size_t)NTOK * Dm];
__device__ float g_o[(size_t)NTOK * Dm];
__device__ float g_y[(size_t)NTOK * Dm];
__device__ float g_z[(size_t)NTOK * Dm];
__device__ float g_h[(size_t)NTOK * DFFn];
// tf32-rounded weight copies
__device__ float g_wq[(size_t)Dm * Dm];
__device__ float g_wk[(size_t)Dm * Dm];
__device__ float g_wv[(size_t)Dm * Dm];
__device__ float g_fc[(size_t)Dm * Dm];
__device__ float g_w1[(size_t)DFFn * Dm];
__device__ float g_w2[(size_t)Dm * DFFn];
// softmax row partial sums + inverse sums
__device__ float g_ps[(size_t)NROWS * 16];
__device__ float g_inv[(size_t)NROWS];

// ---------------- helpers ----------------
__device__ __forceinline__ float rtf32(float x) {
    uint32_t u;
    asm("cvt.rna.tf32.f32 %0, %1;" : "=r"(u) : "f"(x));
    return __uint_as_float(u);
}

__device__ __forceinline__ void mma_tf32(float c[4], const uint32_t a[4], const uint32_t b[2]) {
    asm volatile(
        "mma.sync.aligned.m16n8k8.row.col.f32.tf32.tf32.f32 "
        "{%0,%1,%2,%3}, {%4,%5,%6,%7}, {%8,%9}, {%0,%1,%2,%3};\n"
        : "+f"(c[0]), "+f"(c[1]), "+f"(c[2]), "+f"(c[3])
        : "r"(a[0]), "r"(a[1]), "r"(a[2]), "r"(a[3]), "r"(b[0]), "r"(b[1]));
}

__device__ __forceinline__ uint32_t smem_u32(const void* p) {
    uint32_t a;
    asm("{ .reg .u64 t; cvta.to.shared.u64 t, %1; cvt.u32.u64 %0, t; }"
        : "=r"(a) : "l"(p));
    return a;
}

#define CPG16(dst, src) asm volatile("cp.async.cg.shared.global [%0], [%1], 16;\n" :: "r"(dst), "l"(src))
#define CP_COMMIT() asm volatile("cp.async.commit_group;\n")
#define CP_WAIT2()  asm volatile("cp.async.wait_group 2;\n")

// ---------------- tf32 rounding copy (weights prep) ----------------
__global__ __launch_bounds__(256) void round_copy_kernel(const float* __restrict__ in,
                                                         float* __restrict__ out, int n4)
{
    int i = blockIdx.x * blockDim.x + threadIdx.x;
    int stride = gridDim.x * blockDim.x;
    for (; i < n4; i += stride) {
        float4 v = ((const float4*)in)[i];
        v.x = rtf32(v.x); v.y = rtf32(v.y); v.z = rtf32(v.z); v.w = rtf32(v.w);
        ((float4*)out)[i] = v;
    }
}

// ---------------- LayerNorm ----------------
template <bool ROUND>
__global__ __launch_bounds__(256) void ln_kernel(const float* __restrict__ x,
                                                 const float* __restrict__ g,
                                                 const float* __restrict__ b,
                                                 float* __restrict__ out)
{
    __shared__ float red[256];
    const size_t row = blockIdx.x;
    const int tid = threadIdx.x;
    float4 v = ((const float4*)(x + row * Dm))[tid];

    red[tid] = v.x + v.y + v.z + v.w;
    __syncthreads();
    for (int o = 128; o > 0; o >>= 1) {
        if (tid < o) red[tid] += red[tid + o];
        __syncthreads();
    }
    const float mu = red[0] * (1.0f / Dm);
    __syncthreads();

    const float dx = v.x - mu, dy = v.y - mu, dz = v.z - mu, dw = v.w - mu;
    red[tid] = dx * dx + dy * dy + dz * dz + dw * dw;
    __syncthreads();
    for (int o = 128; o > 0; o >>= 1) {
        if (tid < o) red[tid] += red[tid + o];
        __syncthreads();
    }
    const float inv = rsqrtf(red[0] * (1.0f / Dm) + 1e-6f);

    const float4 gg = ((const float4*)g)[tid];
    const float4 bb = ((const float4*)b)[tid];
    float4 o4;
    o4.x = dx * inv * gg.x + bb.x;
    o4.y = dy * inv * gg.y + bb.y;
    o4.z = dz * inv * gg.z + bb.z;
    o4.w = dw * inv * gg.w + bb.w;
    if (ROUND) {
        o4.x = rtf32(o4.x); o4.y = rtf32(o4.y); o4.z = rtf32(o4.z); o4.w = rtf32(o4.w);
    }
    ((float4*)(out + row * Dm))[tid] = o4;
}

// ============================================================================
// tf32 mma.sync NT GEMM: C[M,N] = A[M,K] @ W[N,K]^T  (A, W pre-rounded)
// BM=256, BN=128, BK=16, 3-stage cp.async, 256 threads (8 warps 4Mx2N),
// warp tile 64x64 (4 m16 x 8 n8), acc = 128 regs.
// EPI: 0=alpha*acc ; 1=acc+resid ; 2=relu(acc+bias) ; 3=acc+bias+resid
// ============================================================================
#define GS 20                       // smem floats per row (16 + 4 pad)
#define G6_A_FLOATS (256 * GS)      // 5120
#define G6_B_FLOATS (128 * GS)      // 2560
#define G6_STAGE_FLOATS (G6_A_FLOATS + G6_B_FLOATS)     // 7680
#define G6_SMEM (3 * G6_STAGE_FLOATS * 4)               // 92160 bytes

template <int EPI, bool ROUND>
__global__ __launch_bounds__(256, 1) void gemm6(const float* __restrict__ A,
                                                const float* __restrict__ W,
                                                float* __restrict__ C,
                                                int M, int N, int K,
                                                const float* __restrict__ bias,
                                                const float* __restrict__ resid,
                                                float alpha)
{
    extern __shared__ __align__(128) float smem[];
    const uint32_t sbase = smem_u32(smem);
    const int tid  = threadIdx.x;
    const int lane = tid & 31;
    const int warp = tid >> 5;
    const int wm = warp >> 1;          // 0..3
    const int wn = warp & 1;           // 0..1
    const int m0 = blockIdx.y * 256;
    const int n0 = blockIdx.x * 128;

    // global load slots
    const float* gAp[4];
    uint32_t aOf[4];
#pragma unroll
    for (int i = 0; i < 4; i++) {
        const int c = i * 256 + tid;          // 0..1023
        const int row = c >> 2, j = c & 3;    // 4 chunks of 4 floats per 16-float row
        gAp[i] = A + (size_t)(m0 + row) * K + j * 4;
        aOf[i] = (row * GS + j * 4) * 4;
    }
    const float* gBp[2];
    uint32_t bOf[2];
#pragma unroll
    for (int i = 0; i < 2; i++) {
        const int c = i * 256 + tid;          // 0..511
        const int row = c >> 2, j = c & 3;
        gBp[i] = W + (size_t)(n0 + row) * K + j * 4;
        bOf[i] = (G6_A_FLOATS + row * GS + j * 4) * 4;
    }

    float acc[4][8][4];
#pragma unroll
    for (int i = 0; i < 4; i++)
#pragma unroll
        for (int j = 0; j < 8; j++)
#pragma unroll
            for (int t = 0; t < 4; t++) acc[i][j][t] = 0.f;

    const int nIter = K >> 4;

#define G6_LOAD(st, kit) do {                                       \
        const uint32_t _b = sbase + (uint32_t)(st) * (G6_STAGE_FLOATS * 4); \
        const int _k = (kit) << 4;                                  \
        CPG16(_b + aOf[0], gAp[0] + _k); CPG16(_b + aOf[1], gAp[1] + _k); \
        CPG16(_b + aOf[2], gAp[2] + _k); CPG16(_b + aOf[3], gAp[3] + _k); \
        CPG16(_b + bOf[0], gBp[0] + _k); CPG16(_b + bOf[1], gBp[1] + _k); \
    } while (0)

    G6_LOAD(0, 0); CP_COMMIT();
    G6_LOAD(1, 1); CP_COMMIT();

    for (int it = 0; it < nIter; ++it) {
        if (it + 2 < nIter) G6_LOAD((it + 2) % 3, it + 2);
        CP_COMMIT();
        CP_WAIT2();
        __syncthreads();

        const float* as = smem + (it % 3) * G6_STAGE_FLOATS;
        const float* bs = as + G6_A_FLOATS;
#pragma unroll
        for (int ks = 0; ks < 2; ks++) {
            const int c = ks * 8 + (lane & 3);
            uint32_t af[4][4], bf[8][2];
#pragma unroll
            for (int mt = 0; mt < 4; mt++) {
                const int r = wm * 64 + mt * 16 + (lane >> 2);
                af[mt][0] = __float_as_uint(as[r * GS + c]);
                af[mt][1] = __float_as_uint(as[(r + 8) * GS + c]);
                af[mt][2] = __float_as_uint(as[r * GS + c + 4]);
                af[mt][3] = __float_as_uint(as[(r + 8) * GS + c + 4]);
            }
#pragma unroll
            for (int nt = 0; nt < 8; nt++) {
                const int n = wn * 64 + nt * 8 + (lane >> 2);
                bf[nt][0] = __float_as_uint(bs[n * GS + c]);
                bf[nt][1] = __float_as_uint(bs[n * GS + c + 4]);
            }
#pragma unroll
            for (int mt = 0; mt < 4; mt++)
#pragma unroll
                for (int nt = 0; nt < 8; nt++)
                    mma_tf32(acc[mt][nt], af[mt], bf[nt]);
        }
        __syncthreads();
    }

    // epilogue
#pragma unroll
    for (int mt = 0; mt < 4; mt++) {
#pragma unroll
        for (int nt = 0; nt < 8; nt++) {
            const int r = m0 + wm * 64 + mt * 16 + (lane >> 2);
            const int cidx = n0 + wn * 64 + nt * 8 + (lane & 3) * 2;
#pragma unroll
            for (int half = 0; half < 2; half++) {
                const int m = r + half * 8;
                float v0 = acc[mt][nt][half * 2 + 0];
                float v1 = acc[mt][nt][half * 2 + 1];
                if (EPI == 0)      { v0 *= alpha; v1 *= alpha; }
                else if (EPI == 1) {
                    const float* rp = resid + (size_t)m * N + cidx;
                    v0 += rp[0]; v1 += rp[1];
                }
                else if (EPI == 2) {
                    v0 = fmaxf(v0 + bias[cidx], 0.f);
                    v1 = fmaxf(v1 + bias[cidx + 1], 0.f);
                }
                else if (EPI == 3) {
                    const float* rp = resid + (size_t)m * N + cidx;
                    v0 += bias[cidx] + rp[0];
                    v1 += bias[cidx + 1] + rp[1];
                }
                if (ROUND) { v0 = rtf32(v0); v1 = rtf32(v1); }
                *(float2*)(C + (size_t)m * N + cidx) = make_float2(v0, v1);
            }
        }
    }
#undef G6_LOAD
}

// ============================================================================
// Scores+exp: e[b,h,q,k] = mask? 0 : exp((Q/8 . K) * prior) ; writes e and
// deterministic per-tile row partial sums to g_ps[row][tile].
// ============================================================================
#define SS 36  // smem stride 32+4
__global__ __launch_bounds__(256) void scores_exp(const float* __restrict__ Q,
                                                  const float* __restrict__ Km,
                                                  const float* __restrict__ prior,
                                                  const int* __restrict__ mask,
                                                  float* __restrict__ attn,
                                                  float* __restrict__ ps)
{
    __shared__ float Qs[128 * SS];
    __shared__ float Ks[128 * SS];
    __shared__ float sp[128][2];
    const int bh = blockIdx.z, b = bh >> 4, h = bh & 15;
    const int m0 = blockIdx.y * 128, n0 = blockIdx.x * 128;
    const int tid = threadIdx.x;
    const int lane = tid & 31;
    const int warp = tid >> 5;
    const int wm = warp >> 1, wn = warp & 1;

    const int lrow = tid >> 1;
    const int lcg  = (tid & 1) * 16;
    const float* Qg = Q + (size_t)(b * Lseq + m0 + lrow) * Dm + h * DKh + lcg;
    const float* Kg = Km + (size_t)(b * Lseq + n0 + lrow) * Dm + h * DKh + lcg;

    float acc[2][8][4];
#pragma unroll
    for (int i = 0; i < 2; i++)
#pragma unroll
        for (int j = 0; j < 8; j++)
#pragma unroll
            for (int t = 0; t < 4; t++) acc[i][j][t] = 0.f;

#pragma unroll
    for (int it = 0; it < 2; it++) {
        const int k0 = it * 32;
#pragma unroll
        for (int j = 0; j < 4; j++) {
            float4 qv = *(const float4*)(Qg + k0 + 4 * j);
            float4 kv = *(const float4*)(Kg + k0 + 4 * j);
            *(float4*)&Qs[lrow * SS + lcg + 4 * j] = qv;
            *(float4*)&Ks[lrow * SS + lcg + 4 * j] = kv;
        }
        __syncthreads();
#pragma unroll
        for (int ks = 0; ks < 4; ks++) {
            const int c = ks * 8 + (lane & 3);
            uint32_t af[2][4], bf[8][2];
#pragma unroll
            for (int mt = 0; mt < 2; mt++) {
                const int r = wm * 32 + mt * 16 + (lane >> 2);
                af[mt][0] = __float_as_uint(Qs[r * SS + c]);
                af[mt][1] = __float_as_uint(Qs[(r + 8) * SS + c]);
                af[mt][2] = __float_as_uint(Qs[r * SS + c + 4]);
                af[mt][3] = __float_as_uint(Qs[(r + 8) * SS + c + 4]);
            }
#pragma unroll
            for (int nt = 0; nt < 8; nt++) {
                const int n = wn * 64 + nt * 8 + (lane >> 2);
                bf[nt][0] = __float_as_uint(Ks[n * SS + c]);
                bf[nt][1] = __float_as_uint(Ks[n * SS + c + 4]);
            }
#pragma unroll
            for (int mt = 0; mt < 2; mt++)
#pragma unroll
                for (int nt = 0; nt < 8; nt++)
                    mma_tf32(acc[mt][nt], af[mt], bf[nt]);
        }
        __syncthreads();
    }

    float lsum[2][2] = {{0.f, 0.f}, {0.f, 0.f}};
    float* abase = attn + (size_t)bh * Lseq * Lseq;
#pragma unroll
    for (int mt = 0; mt < 2; mt++) {
#pragma unroll
        for (int nt = 0; nt < 8; nt++) {
            const int r = m0 + wm * 32 + mt * 16 + (lane >> 2);
            const int cidx = n0 + wn * 64 + nt * 8 + (lane & 3) * 2;
            const bool k0m = (mask[b * Lseq + cidx] == 0);
            const bool k1m = (mask[b * Lseq + cidx + 1] == 0);
#pragma unroll
            for (int half = 0; half < 2; half++) {
                const int q = r + half * 8;
                const float* pr = prior + ((size_t)b * Lseq + q) * Lseq + cidx;
                float v0 = k0m ? 0.f : expf(acc[mt][nt][half * 2 + 0] * pr[0]);
                float v1 = k1m ? 0.f : expf(acc[mt][nt][half * 2 + 1] * pr[1]);
                *(float2*)(abase + (size_t)q * Lseq + cidx) = make_float2(v0, v1);
                lsum[mt][half] += v0 + v1;
            }
        }
    }

    // reduce within quads (lane&3 varies cols, same row)
#pragma unroll
    for (int mt = 0; mt < 2; mt++)
#pragma unroll
        for (int half = 0; half < 2; half++) {
            float s = lsum[mt][half];
            s += __shfl_xor_sync(0xFFFFFFFF, s, 1);
            s += __shfl_xor_sync(0xFFFFFFFF, s, 2);
            if ((lane & 3) == 0)
                sp[wm * 32 + mt * 16 + half * 8 + (lane >> 2)][wn] = s;
        }
    __syncthreads();
    if (tid < 128) {
        const float p = sp[tid][0] + sp[tid][1];
        ps[((size_t)bh * Lseq + m0 + tid) * 16 + blockIdx.x] = p;
    }
}

// ---------------- rowsum -> inverse ----------------
__global__ __launch_bounds__(256) void rowsum_inv(const float* __restrict__ ps,
                                                  float* __restrict__ inv)
{
    const int r = blockIdx.x * 256 + threadIdx.x;
    if (r >= NROWS) return;
    const float4* p = (const float4*)(ps + (size_t)r * 16);
    float4 a = p[0], b = p[1], c = p[2], d = p[3];
    float s = ((a.x + a.y) + (a.z + a.w)) + ((b.x + b.y) + (b.z + b.w))
            + ((c.x + c.y) + (c.z + c.w)) + ((d.x + d.y) + (d.z + d.w));
    inv[r] = 1.0f / s;
}

// ============================================================================
// AV + normalize: reads e, n = e*inv (written back as final attn),
// O = n @ V (tf32 mma).
// ============================================================================
__global__ __launch_bounds__(256) void av_tc(float* __restrict__ attn,
                                             const float* __restrict__ V,
                                             const float* __restrict__ rinv,
                                             float* __restrict__ O)
{
    __shared__ float Ss[128 * SS];
    __shared__ float Vs[64 * SS];
    const int bh = blockIdx.z, b = bh >> 4, h = bh & 15;
    const int m0 = blockIdx.y * 128;
    const int tid = threadIdx.x;
    const int lane = tid & 31;
    const int warp = tid >> 5;
    const int wm = warp >> 1, wn = warp & 1;

    const int lrow = tid >> 1;
    const int lcg  = (tid & 1) * 16;
    float* Sg = attn + (size_t)bh * Lseq * Lseq + (size_t)(m0 + lrow) * Lseq + lcg;
    const float* Vg = V + (size_t)((size_t)b * Lseq + lane) * Dm + h * DKh + warp * 8;
    const float inv = rinv[(size_t)bh * Lseq + m0 + lrow];

    float acc[2][4][4];
#pragma unroll
    for (int i = 0; i < 2; i++)
#pragma unroll
        for (int j = 0; j < 4; j++)
#pragma unroll
            for (int t = 0; t < 4; t++) acc[i][j][t] = 0.f;

    for (int k0 = 0; k0 < Lseq; k0 += 32) {
#pragma unroll
        for (int j = 0; j < 4; j++) {
            float4 sv = *(const float4*)(Sg + k0 + 4 * j);
            sv.x *= inv; sv.y *= inv; sv.z *= inv; sv.w *= inv;
            *(float4*)(Sg + k0 + 4 * j) = sv;   // final normalized attn
            sv.x = rtf32(sv.x); sv.y = rtf32(sv.y);
            sv.z = rtf32(sv.z); sv.w = rtf32(sv.w);
            *(float4*)&Ss[lrow * SS + lcg + 4 * j] = sv;
        }
        {
            const float* vp = Vg + (size_t)k0 * Dm;
            float4 a = *(const float4*)vp;
            float4 c = *(const float4*)(vp + 4);
            const int d0 = warp * 8;
            Vs[(d0 + 0) * SS + lane] = a.x;
            Vs[(d0 + 1) * SS + lane] = a.y;
            Vs[(d0 + 2) * SS + lane] = a.z;
            Vs[(d0 + 3) * SS + lane] = a.w;
            Vs[(d0 + 4) * SS + lane] = c.x;
            Vs[(d0 + 5) * SS + lane] = c.y;
            Vs[(d0 + 6) * SS + lane] = c.z;
            Vs[(d0 + 7) * SS + lane] = c.w;
        }
        __syncthreads();
#pragma unroll
        for (int ks = 0; ks < 4; ks++) {
            const int c = ks * 8 + (lane & 3);
            uint32_t af[2][4], bf[4][2];
#pragma unroll
            for (int mt = 0; mt < 2; mt++) {
                const int r = wm * 32 + mt * 16 + (lane >> 2);
                af[mt][0] = __float_as_uint(Ss[r * SS + c]);
                af[mt][1] = __float_as_uint(Ss[(r + 8) * SS + c]);
                af[mt][2] = __float_as_uint(Ss[r * SS + c + 4]);
                af[mt][3] = __float_as_uint(Ss[(r + 8) * SS + c + 4]);
            }
#pragma unroll
            for (int nt = 0; nt < 4; nt++) {
                const int n = wn * 32 + nt * 8 + (lane >> 2);
                bf[nt][0] = __float_as_uint(Vs[n * SS + c]);
                bf[nt][1] = __float_as_uint(Vs[n * SS + c + 4]);
            }
#pragma unroll
            for (int mt = 0; mt < 2; mt++)
#pragma unroll
                for (int nt = 0; nt < 4; nt++)
                    mma_tf32(acc[mt][nt], af[mt], bf[nt]);
        }
        __syncthreads();
    }

#pragma unroll
    for (int mt = 0; mt < 2; mt++) {
#pragma unroll
        for (int nt = 0; nt < 4; nt++) {
            const int r = m0 + wm * 32 + mt * 16 + (lane >> 2);
            const int d = wn * 32 + nt * 8 + (lane & 3) * 2;
#pragma unroll
            for (int half = 0; half < 2; half++) {
                const int q = r + half * 8;
                float v0 = rtf32(acc[mt][nt][half * 2 + 0]);
                float v1 = rtf32(acc[mt][nt][half * 2 + 1]);
                *(float2*)(O + (size_t)((size_t)b * Lseq + q) * Dm + h * DKh + d)
                    = make_float2(v0, v1);
            }
        }
    }
}

// ---------------- launch ----------------
extern "C" void kernel_launch(void* const* d_in, const int* in_sizes, int n_in,
                              void* d_out, int out_size)
{
    const float* src   = (const float*)d_in[0];
    const int*   mask  = (const int*)d_in[1];
    const float* prior = (const float*)d_in[2];
    const float* ln1_g = (const float*)d_in[3];
    const float* ln1_b = (const float*)d_in[4];
    const float* wq    = (const float*)d_in[5];
    const float* wk    = (const float*)d_in[6];
    const float* wv    = (const float*)d_in[7];
    const float* fc_w  = (const float*)d_in[8];
    const float* ln2_g = (const float*)d_in[9];
    const float* ln2_b = (const float*)d_in[10];
    const float* w1_w  = (const float*)d_in[11];
    const float* w1_b  = (const float*)d_in[12];
    const float* w2_w  = (const float*)d_in[13];
    const float* w2_b  = (const float*)d_in[14];

    float* out_y    = (float*)d_out;                       // [B,L,D]
    float* out_attn = out_y + (size_t)NTOK * Dm;           // [B,H,L,L]

    float *x, *q, *k, *v, *o, *y, *z, *hb, *ps, *rinv;
    float *rwq, *rwk, *rwv, *rfc, *rw1, *rw2;
    cudaGetSymbolAddress((void**)&x,  g_x);
    cudaGetSymbolAddress((void**)&q,  g_q);
    cudaGetSymbolAddress((void**)&k,  g_k);
    cudaGetSymbolAddress((void**)&v,  g_v);
    cudaGetSymbolAddress((void**)&o,  g_o);
    cudaGetSymbolAddress((void**)&y,  g_y);
    cudaGetSymbolAddress((void**)&z,  g_z);
    cudaGetSymbolAddress((void**)&hb, g_h);
    cudaGetSymbolAddress((void**)&ps, g_ps);
    cudaGetSymbolAddress((void**)&rinv, g_inv);
    cudaGetSymbolAddress((void**)&rwq, g_wq);
    cudaGetSymbolAddress((void**)&rwk, g_wk);
    cudaGetSymbolAddress((void**)&rwv, g_wv);
    cudaGetSymbolAddress((void**)&rfc, g_fc);
    cudaGetSymbolAddress((void**)&rw1, g_w1);
    cudaGetSymbolAddress((void**)&rw2, g_w2);

    cudaFuncSetAttribute(gemm6<0, true>,  cudaFuncAttributeMaxDynamicSharedMemorySize, G6_SMEM);
    cudaFuncSetAttribute(gemm6<1, false>, cudaFuncAttributeMaxDynamicSharedMemorySize, G6_SMEM);
    cudaFuncSetAttribute(gemm6<2, true>,  cudaFuncAttributeMaxDynamicSharedMemorySize, G6_SMEM);
    cudaFuncSetAttribute(gemm6<3, false>, cudaFuncAttributeMaxDynamicSharedMemorySize, G6_SMEM);

    // 0) tf32-round weight copies
    const int nD = (Dm * Dm) / 4, nF = (DFFn * Dm) / 4;
    round_copy_kernel<<<256, 256>>>(wq,   rwq, nD);
    round_copy_kernel<<<256, 256>>>(wk,   rwk, nD);
    round_copy_kernel<<<256, 256>>>(wv,   rwv, nD);
    round_copy_kernel<<<256, 256>>>(fc_w, rfc, nD);
    round_copy_kernel<<<512, 256>>>(w1_w, rw1, nF);
    round_copy_kernel<<<512, 256>>>(w2_w, rw2, nF);

    // 1) pre-LN (tf32-rounded output)
    ln_kernel<true><<<NTOK, 256>>>(src, ln1_g, ln1_b, x);

    // 2) QKV projections (Q pre-scaled by 1/8)
    dim3 gD(Dm / 128, NTOK / 256);
    gemm6<0, true><<<gD, 256, G6_SMEM>>>(x, rwq, q, NTOK, Dm, Dm, nullptr, nullptr, 0.125f);
    gemm6<0, true><<<gD, 256, G6_SMEM>>>(x, rwk, k, NTOK, Dm, Dm, nullptr, nullptr, 1.0f);
    gemm6<0, true><<<gD, 256, G6_SMEM>>>(x, rwv, v, NTOK, Dm, Dm, nullptr, nullptr, 1.0f);

    // 3) scores + prior + mask + exp -> e in attn region, partial row sums
    dim3 gS(Lseq / 128, Lseq / 128, Bsz * Hn);
    scores_exp<<<gS, 256>>>(q, k, prior, mask, out_attn, ps);

    // 4) row sums -> inverses
    rowsum_inv<<<NROWS / 256, 256>>>(ps, rinv);

    // 5) normalize (writes final attn) + O = attn @ V
    dim3 gAV(1, Lseq / 128, Bsz * Hn);
    av_tc<<<gAV, 256>>>(out_attn, v, rinv, o);

    // 6) y = O @ fc^T + src
    gemm6<1, false><<<gD, 256, G6_SMEM>>>(o, rfc, y, NTOK, Dm, Dm, nullptr, src, 1.0f);

    // 7) FFN: z = LN(y); h = relu(z@w1^T + b1); out_y = h@w2^T + b2 + y
    ln_kernel<true><<<NTOK, 256>>>(y, ln2_g, ln2_b, z);
    dim3 gF(DFFn / 128, NTOK / 256);
    gemm6<2, true><<<gF, 256, G6_SMEM>>>(z, rw1, hb, NTOK, DFFn, Dm, w1_b, nullptr, 1.0f);
    gemm6<3, false><<<gD, 256, G6_SMEM>>>(hb, rw2, out_y, NTOK, Dm, DFFn, w2_b, y, 1.0f);
}